// round 8
// baseline (speedup 1.0000x reference)
#include <cuda_runtime.h>
#include <cuda_fp16.h>
#include <cstdint>
#include <mma.h>
#include <math.h>

using namespace nvcuda;

#define T_TOK 4096
#define HDIM  2048
#define IDIM  4096
#define NEXP  8
#define TOPK  4
#define CAP   4096

// GEMM tiling
#define BM 128
#define BN 128
#define BK 64
#define NST 3
#define LDAH 72                    // halves (64 + 8 pad) -> 144B rows
#define LDBH 136                   // halves (128 + 8 pad) -> 272B rows
#define A_ST (BM * LDAH)           // halves
#define B_ST (BK * LDBH)           // halves
#define ST_H (A_ST + B_ST)         // halves per stage
#define LDC  132                   // fp32 epilogue stage stride
#define SMEM_REQ (NST * ST_H * 2 + 512)

// ---------------- scratch (device globals: allocation-free) ------------------
__device__ int    g_counts[NEXP];
__device__ int    g_tok[NEXP * CAP];
__device__ int    g_slot_epos[T_TOK * TOPK];
__device__ float  g_slot_gate[T_TOK * TOPK];
__device__ __half g_xh [(size_t)T_TOK * HDIM];
__device__ __half g_w1h[(size_t)NEXP * HDIM * IDIM];
__device__ __half g_w2h[(size_t)NEXP * IDIM * IDIM];
__device__ __half g_w3h[(size_t)NEXP * IDIM * HDIM];
__device__ __half g_h1 [(size_t)NEXP * CAP * IDIM];
__device__ __half g_h2 [(size_t)NEXP * CAP * IDIM];
__device__ __half g_y  [(size_t)NEXP * CAP * HDIM];

// ---------------- helpers ----------------------------------------------------
__device__ __forceinline__ void cp16(void* smem_ptr, const void* gptr) {
    unsigned int s = (unsigned int)__cvta_generic_to_shared(smem_ptr);
    asm volatile("cp.async.cg.shared.global [%0], [%1], 16;" :: "r"(s), "l"(gptr));
}
__device__ __forceinline__ void cp_commit() {
    asm volatile("cp.async.commit_group;");
}

// ---------------- init / fp32->fp16 convert ---------------------------------
__global__ void init_kernel() {
    if (threadIdx.x < NEXP) g_counts[threadIdx.x] = 0;
}

__global__ void cvt_kernel(const float4* __restrict__ src,
                           __half2* __restrict__ dst, int n4) {
    int i = blockIdx.x * blockDim.x + threadIdx.x;
    if (i >= n4) return;
    float4 v = src[i];
    dst[2 * i]     = __floats2half2_rn(v.x, v.y);
    dst[2 * i + 1] = __floats2half2_rn(v.z, v.w);
}

// ---------------- router: 1 warp per token (fp32, matches reference) ---------
__global__ void router_kernel(const float* __restrict__ x,
                              const float* __restrict__ rw) {
    int gtid = blockIdx.x * blockDim.x + threadIdx.x;
    int tok  = gtid >> 5;
    int lane = gtid & 31;
    if (tok >= T_TOK) return;

    const float* xr = x + (size_t)tok * HDIM;
    float acc[NEXP];
#pragma unroll
    for (int e = 0; e < NEXP; e++) acc[e] = 0.f;
    for (int h = lane; h < HDIM; h += 32) {
        float xv = xr[h];
        const float* r = rw + (size_t)h * NEXP;
#pragma unroll
        for (int e = 0; e < NEXP; e++) acc[e] = fmaf(xv, r[e], acc[e]);
    }
#pragma unroll
    for (int off = 16; off; off >>= 1)
#pragma unroll
        for (int e = 0; e < NEXP; e++)
            acc[e] += __shfl_down_sync(0xffffffffu, acc[e], off);

    if (lane == 0) {
        float mx = acc[0];
#pragma unroll
        for (int e = 1; e < NEXP; e++) mx = fmaxf(mx, acc[e]);
        float p[NEXP];
#pragma unroll
        for (int e = 0; e < NEXP; e++) p[e] = acc[e];
        int sel[TOPK]; float g[TOPK]; float s = 0.f;
#pragma unroll
        for (int k = 0; k < TOPK; k++) {
            int best = 0; float bv = -INFINITY;
#pragma unroll
            for (int e = 0; e < NEXP; e++)
                if (p[e] > bv) { bv = p[e]; best = e; }
            sel[k] = best; g[k] = expf(bv - mx); s += g[k]; p[best] = -INFINITY;
        }
        float inv = 1.f / s;
#pragma unroll
        for (int k = 0; k < TOPK; k++) {
            int e = sel[k];
            int pos = atomicAdd(&g_counts[e], 1);
            g_tok[e * CAP + pos]        = tok;
            g_slot_epos[tok * TOPK + k] = e * CAP + pos;
            g_slot_gate[tok * TOPK + k] = g[k] * inv;
        }
    }
}

// ---------------- fp16 pipelined grouped GEMM --------------------------------
// Single-sync multistage: wait stage ready -> sync -> issue next loads -> compute.
// PHASE 0: H1 = silu(gather(Xh) @ W1h)   K=2048 N=4096
// PHASE 1: H2 = silu(H1 @ W2h)           K=4096 N=4096
// PHASE 2: Y  = H2 @ W3h                 K=4096 N=2048
template<int PHASE>
__global__ void __launch_bounds__(128)
gemm_hk(const __half* __restrict__ Wh) {
    constexpr int  K    = (PHASE == 0) ? HDIM : IDIM;
    constexpr int  N    = (PHASE == 2) ? HDIM : IDIM;
    constexpr int  KT   = K / BK;
    constexpr bool GATH = (PHASE == 0);
    constexpr bool SILU = (PHASE < 2);

    const int e       = blockIdx.z;
    const int n_e     = g_counts[e];
    const int rowBase = blockIdx.y * BM;
    if (rowBase >= n_e) return;
    const int colBase = blockIdx.x * BN;
    const int tid     = threadIdx.x;
    const int wid     = tid >> 5;

    extern __shared__ __half sh[];
    int* srow = (int*)(sh + NST * ST_H);

    {
        int r = rowBase + tid;
        if (r >= n_e) r = n_e - 1;
        srow[tid] = GATH ? g_tok[e * CAP + r] : r;
    }
    __syncthreads();

    const __half* Aptr;
    __half* C;
    if (PHASE == 0)      { Aptr = g_xh;                          C = g_h1 + (size_t)e * CAP * IDIM; }
    else if (PHASE == 1) { Aptr = g_h1 + (size_t)e * CAP * IDIM; C = g_h2 + (size_t)e * CAP * IDIM; }
    else                 { Aptr = g_h2 + (size_t)e * CAP * IDIM; C = g_y  + (size_t)e * CAP * HDIM; }
    const __half* Wp = Wh + (size_t)e * K * N;

    // producer coords
    const int am = tid >> 3, aq = tid & 7;     // A: 16 rows x 8 chunks, x8 iters
    const int bk = tid >> 4, bq = tid & 15;    // B: 8 rows x 16 chunks, x8 iters
    int arow[8];
#pragma unroll
    for (int i = 0; i < 8; i++) arow[i] = srow[am + 16 * i];

#define LOAD_STAGE(ST, K0)                                                         \
    {                                                                              \
        __half* dA = sh + (ST) * ST_H;                                             \
        __half* dB = dA + A_ST;                                                    \
        _Pragma("unroll")                                                          \
        for (int i = 0; i < 8; i++) {                                              \
            int m = am + 16 * i;                                                   \
            cp16(dA + m * LDAH + aq * 8,                                           \
                 Aptr + (size_t)arow[i] * K + (K0) + aq * 8);                      \
        }                                                                          \
        _Pragma("unroll")                                                          \
        for (int i = 0; i < 8; i++) {                                              \
            int kk = bk + 8 * i;                                                   \
            cp16(dB + kk * LDBH + bq * 8,                                          \
                 Wp + (size_t)((K0) + kk) * N + colBase + bq * 8);                 \
        }                                                                          \
    }

    const int wr = (wid >> 1) * 64;
    const int wc = (wid & 1)  * 64;

    wmma::fragment<wmma::accumulator, 16, 16, 16, float> acc[4][4];
#pragma unroll
    for (int i = 0; i < 4; i++)
#pragma unroll
        for (int j = 0; j < 4; j++) wmma::fill_fragment(acc[i][j], 0.f);

    // prologue: stages 0..NST-2
#pragma unroll
    for (int s = 0; s < NST - 1; s++) { LOAD_STAGE(s, s * BK); cp_commit(); }

    for (int ct = 0; ct < KT; ct++) {
        asm volatile("cp.async.wait_group %0;" :: "n"(NST - 2));
        __syncthreads();   // stage ct ready; all warps done with stage ct-1

        int pf = ct + NST - 1;                 // goes into slot (ct-1)%NST
        if (pf < KT) LOAD_STAGE(pf % NST, pf * BK);
        cp_commit();

        const __half* a0 = sh + (ct % NST) * ST_H + wr * LDAH;
        const __half* b0 = sh + (ct % NST) * ST_H + A_ST + wc;
#pragma unroll
        for (int kk = 0; kk < BK; kk += 16) {
            wmma::fragment<wmma::matrix_a, 16, 16, 16, half, wmma::row_major> af[4];
            wmma::fragment<wmma::matrix_b, 16, 16, 16, half, wmma::row_major> bf[4];
#pragma unroll
            for (int i = 0; i < 4; i++)
                wmma::load_matrix_sync(af[i], a0 + i * 16 * LDAH + kk, LDAH);
#pragma unroll
            for (int j = 0; j < 4; j++)
                wmma::load_matrix_sync(bf[j], b0 + kk * LDBH + j * 16, LDBH);
#pragma unroll
            for (int i = 0; i < 4; i++)
#pragma unroll
                for (int j = 0; j < 4; j++)
                    wmma::mma_sync(acc[i][j], af[i], bf[j], acc[i][j]);
        }
    }

    // epilogue: stage fp32 in smem, SiLU, convert, half2 stores
    __syncthreads();
    float* sC = (float*)sh;
#pragma unroll
    for (int i = 0; i < 4; i++)
#pragma unroll
        for (int j = 0; j < 4; j++)
            wmma::store_matrix_sync(sC + (wr + i * 16) * LDC + wc + j * 16,
                                    acc[i][j], LDC, wmma::mem_row_major);
    __syncthreads();

    const bool full = (rowBase + BM) <= n_e;
    for (int idx = tid; idx < BM * (BN / 2); idx += 128) {
        int row = idx >> 6;
        int cp  = idx & 63;
        int gr  = rowBase + row;
        if (full || gr < n_e) {
            float f0 = sC[row * LDC + 2 * cp];
            float f1 = sC[row * LDC + 2 * cp + 1];
            if (SILU) {
                f0 = f0 / (1.f + expf(-f0));
                f1 = f1 / (1.f + expf(-f1));
            }
            ((__half2*)(C + (size_t)gr * N + colBase))[cp] = __floats2half2_rn(f0, f1);
        }
    }
}

// ---------------- deterministic combine -------------------------------------
__global__ void combine_kernel(float* __restrict__ out) {
    int idx   = blockIdx.x * blockDim.x + threadIdx.x;
    int total = T_TOK * (HDIM / 2);
    if (idx >= total) return;
    int t  = idx / (HDIM / 2);
    int hp = idx % (HDIM / 2);

    float sx = 0.f, sy = 0.f;
#pragma unroll
    for (int k = 0; k < TOPK; k++) {
        int   ep = g_slot_epos[t * TOPK + k];
        float gk = g_slot_gate[t * TOPK + k];
        __half2 y = ((const __half2*)(g_y + (size_t)ep * HDIM))[hp];
        float2 yf = __half22float2(y);
        sx += gk * yf.x;
        sy += gk * yf.y;
    }
    ((float2*)(out + (size_t)t * HDIM))[hp] = make_float2(sx, sy);
}

// ---------------- launch -----------------------------------------------------
extern "C" void kernel_launch(void* const* d_in, const int* in_sizes, int n_in,
                              void* d_out, int out_size) {
    const float* x  = (const float*)d_in[0];
    const float* rw = (const float*)d_in[1];
    const float* w1 = (const float*)d_in[2];
    const float* w2 = (const float*)d_in[3];
    const float* w3 = (const float*)d_in[4];
    float* out = (float*)d_out;

    cudaFuncSetAttribute(gemm_hk<0>, cudaFuncAttributeMaxDynamicSharedMemorySize, SMEM_REQ);
    cudaFuncSetAttribute(gemm_hk<1>, cudaFuncAttributeMaxDynamicSharedMemorySize, SMEM_REQ);
    cudaFuncSetAttribute(gemm_hk<2>, cudaFuncAttributeMaxDynamicSharedMemorySize, SMEM_REQ);

    init_kernel<<<1, 32>>>();

    // fp32 -> fp16 conversions
    __half *xh, *w1h, *w2h, *w3h;
    cudaGetSymbolAddress((void**)&xh,  g_xh);
    cudaGetSymbolAddress((void**)&w1h, g_w1h);
    cudaGetSymbolAddress((void**)&w2h, g_w2h);
    cudaGetSymbolAddress((void**)&w3h, g_w3h);

    int n4x  = T_TOK * HDIM / 4;
    int n4w1 = NEXP * HDIM * IDIM / 4;
    int n4w2 = NEXP * IDIM * IDIM / 4;
    int n4w3 = NEXP * IDIM * HDIM / 4;
    cvt_kernel<<<(n4x  + 255) / 256, 256>>>((const float4*)x,  (__half2*)xh,  n4x);
    cvt_kernel<<<(n4w1 + 255) / 256, 256>>>((const float4*)w1, (__half2*)w1h, n4w1);
    cvt_kernel<<<(n4w2 + 255) / 256, 256>>>((const float4*)w2, (__half2*)w2h, n4w2);
    cvt_kernel<<<(n4w3 + 255) / 256, 256>>>((const float4*)w3, (__half2*)w3h, n4w3);

    router_kernel<<<(T_TOK * 32) / 128, 128>>>(x, rw);

    dim3 blk(128);
    gemm_hk<0><<<dim3(IDIM / BN, CAP / BM, NEXP), blk, SMEM_REQ>>>(w1h);
    gemm_hk<1><<<dim3(IDIM / BN, CAP / BM, NEXP), blk, SMEM_REQ>>>(w2h);
    gemm_hk<2><<<dim3(HDIM / BN, CAP / BM, NEXP), blk, SMEM_REQ>>>(w3h);

    combine_kernel<<<(T_TOK * (HDIM / 2) + 255) / 256, 256>>>(out);
}